// round 16
// baseline (speedup 1.0000x reference)
#include <cuda_runtime.h>
#include <cuda_fp16.h>
#include <cstdint>

#define N_NODES 50000
#define N_EDGES 800000
#define D 128
#define N_GRAPHS 512
#define N_CONVS 5
#define EPS 1e-5f

#define N_BLKS 196                  // ceil(50000/256)
#define OFF_SZ (N_BLKS * 256)       // 50176
#define SCAN_GRID 512               // 196 scan CTAs + 316 prologue-only CTAs

typedef unsigned long long u64;
typedef unsigned int u32;

// PDL: overlap dependent-kernel dispatch/prologue with predecessor execution.
// Contract: launch_dependents is executed AFTER this kernel's own pdl_wait
// (or at entry for the first kernel), so a successor's pre-wait code may only
// read data produced >= 2 dependency-steps back (transitively complete).
__device__ __forceinline__ void pdl_wait() {
    asm volatile("griddepcontrol.wait;" ::: "memory");
}
__device__ __forceinline__ void pdl_launch_dependents() {
    asm volatile("griddepcontrol.launch_dependents;" ::: "memory");
}

// ---------------- scratch (static device globals; no allocation) -------------
// NOTE: g_cnt is left zeroed at the END of each run (k_final), and g_ticket is
// reset by the last scan CTA of k_scan1, so every replay starts clean; device
// globals are zero-initialized at module load, so the first run is clean too.
__device__ int    g_cnt[N_NODES];
__device__ int    g_off[OFF_SZ];    // block-local exclusive offsets
__device__ int    g_bsum[N_BLKS];   // per-block sums
__device__ int    g_bpref[N_BLKS];  // exclusive prefix of block sums
__device__ int    g_ticket;         // last-CTA election for scan phase 2
__device__ int    g_slot[N_EDGES];  // packed (slot<<16) | dst
__device__ int    g_ssrc[N_EDGES];
__device__ __half g_x16[(size_t)N_NODES * D];
__device__ __half g_agg16[(size_t)N_NODES * D];
__device__ __half g_h16[(size_t)N_NODES * D];
__device__ __half g_B16[256 * D];   // folded weights, k-major: B[k][j], fp16
__device__ float  g_br[D];          // folded bias (fp32)
__device__ float  g_bnsum[D];
__device__ float  g_bnsq[D];

// ---------------- K1: pure degree count (slot-recording) ---------------------
// Latency/atomic-bound; executes launch_dependents at ENTRY so k_scan1's CTAs
// launch immediately and their prologue (fold+convert) co-runs with this.
__global__ void k_count(const int* __restrict__ dst) {
    pdl_launch_dependents();
    int i = blockIdx.x * blockDim.x + threadIdx.x;
    if (i < N_EDGES) {
        int d = dst[i];
        int slot = atomicAdd(&g_cnt[d], 1);     // max degree << 65536 here
        g_slot[i] = (slot << 16) | d;           // d < 65536
    }
}

// ---------------- K2: [prologue: fold + x->fp16 + BN zero] + scan ------------
// All SCAN_GRID CTAs run the grid-stride prologue BEFORE pdl_wait (inputs are
// harness tensors only -> co-runs with k_count). Blocks >= N_BLKS then exit;
// blocks < N_BLKS wait for g_cnt and perform the hierarchical scan.
#define BFOLD     (256 * D)                      // 32768
#define X4_TOTAL  ((N_NODES * D) / 4)            // 1600000
#define PRO_TOTAL (BFOLD + D + 2 * D + X4_TOTAL)
__global__ void k_scan1(const float* __restrict__ x,
                        const float* __restrict__ Wrel,
                        const float* __restrict__ brel,
                        const float* __restrict__ Wroot) {
    __shared__ int wsum[8];
    const int t = threadIdx.x;
    const int lane = t & 31, w = t >> 5;

    // ---- pre-wait prologue (independent of k_count) ----
    for (int i = blockIdx.x * 256 + t; i < PRO_TOTAL; i += SCAN_GRID * 256) {
        if (i < BFOLD) {
            int k = i >> 7;          // 0..255 (A column)
            int j = i & 127;         // output feature
            float s = 0.f;
            if (k < D) {             // x half pairs with W_root
                #pragma unroll
                for (int c = 0; c < N_CONVS; c++) s += Wroot[c * D * D + j * D + k];
            } else {                 // agg half pairs with W_rel
                int kk = k - D;
                #pragma unroll
                for (int c = 0; c < N_CONVS; c++) s += Wrel[c * D * D + j * D + kk];
            }
            g_B16[i] = __float2half_rn(s);
        } else if (i < BFOLD + D) {
            int j = i - BFOLD;
            float s = 0.f;
            #pragma unroll
            for (int c = 0; c < N_CONVS; c++) s += brel[c * D + j];
            g_br[j] = s;
        } else if (i < BFOLD + 3 * D) {
            int j = i - (BFOLD + D);
            if (j < D) g_bnsum[j] = 0.f; else g_bnsq[j - D] = 0.f;
        } else {
            int e4 = i - (BFOLD + 3 * D);
            float4 v = ((const float4*)x)[e4];
            __half2* o = (__half2*)g_x16;
            o[e4 * 2]     = __floats2half2_rn(v.x, v.y);
            o[e4 * 2 + 1] = __floats2half2_rn(v.z, v.w);
        }
    }
    if (blockIdx.x >= N_BLKS) return;   // prologue-only CTAs

    pdl_wait();                        // g_cnt must be final
    pdl_launch_dependents();

    const int idx = blockIdx.x * 256 + t;
    int v = (idx < N_NODES) ? g_cnt[idx] : 0;
    int incl = v;
    #pragma unroll
    for (int d = 1; d < 32; d <<= 1) {
        int u = __shfl_up_sync(0xffffffffu, incl, d);
        if (lane >= d) incl += u;
    }
    if (lane == 31) wsum[w] = incl;
    __syncthreads();
    if (t < 8) {
        int x2 = wsum[t];
        int xi = x2;
        #pragma unroll
        for (int d = 1; d < 8; d <<= 1) {
            int u = __shfl_up_sync(0xffu, xi, d);
            if (t >= d) xi += u;
        }
        wsum[t] = xi;                  // inclusive warp-sum prefix
    }
    __syncthreads();
    int base = (w == 0) ? 0 : wsum[w - 1];
    g_off[idx] = base + incl - v;      // block-local exclusive
    if (t == 255) g_bsum[blockIdx.x] = wsum[7];

    // ---- phase 2: last scan CTA scans block sums ----
    __shared__ int is_last;
    __threadfence();                   // release g_bsum write
    if (t == 0) {
        int tk = atomicAdd(&g_ticket, 1);
        is_last = (tk == N_BLKS - 1);
    }
    __syncthreads();
    if (!is_last) return;
    __threadfence();                   // acquire all g_bsum writes

    int bv = (t < N_BLKS) ? g_bsum[t] : 0;
    int bincl = bv;
    #pragma unroll
    for (int d = 1; d < 32; d <<= 1) {
        int u = __shfl_up_sync(0xffffffffu, bincl, d);
        if (lane >= d) bincl += u;
    }
    __syncthreads();                   // wsum reuse safe
    if (lane == 31) wsum[w] = bincl;
    __syncthreads();
    if (t < 8) {
        int x2 = wsum[t];
        int xi = x2;
        #pragma unroll
        for (int d = 1; d < 8; d <<= 1) {
            int u = __shfl_up_sync(0xffu, xi, d);
            if (t >= d) xi += u;
        }
        wsum[t] = xi;
    }
    __syncthreads();
    int bbase = (w == 0) ? 0 : wsum[w - 1];
    if (t < N_BLKS) g_bpref[t] = bbase + bincl - bv;
    if (t == 0) g_ticket = 0;          // reset for next replay
}

// ---------------- K3: scatter edges into CSR (no atomics, packed slot) -------
__global__ void k_scatter(const int* __restrict__ src) {
    int i = blockIdx.x * blockDim.x + threadIdx.x;
    // pre-wait prologue: g_slot/src are k_count outputs (2 steps back)
    u32 pk = 0; int sv = 0;
    if (i < N_EDGES) { pk = (u32)g_slot[i]; sv = src[i]; }
    pdl_wait();                        // g_off/g_bpref (scan1) must be final
    pdl_launch_dependents();
    if (i < N_EDGES) {
        int d = pk & 0xFFFFu;
        int p = g_off[d] + g_bpref[d >> 8] + (int)(pk >> 16);
        g_ssrc[p] = sv;
    }
}

// ---------------- K4: aggregate (warp per node, packed f32x2 adds) -----------
// R12-proven: flat statically-unrollable loop, packed add.rn.f32x2 accumulate.
__global__ void k_agg() {
    int warp = (blockIdx.x * blockDim.x + threadIdx.x) >> 5;
    int lane = threadIdx.x & 31;
    // pre-wait prologue: g_off/g_bpref are scan1 outputs (2 steps back)
    int e0 = 0, e1 = 0;
    if (warp < N_NODES) {
        e0 = g_off[warp] + g_bpref[warp >> 8];
        e1 = g_off[warp + 1] + g_bpref[(warp + 1) >> 8];
    }
    pdl_wait();                        // g_ssrc (scatter) must be final
    pdl_launch_dependents();
    if (warp >= N_NODES) return;

    u64 a01 = 0ull, a23 = 0ull;        // packed (f32,f32) accumulators
    for (int b = e0; b < e1; b += 32) {
        int cnt = min(32, e1 - b);
        int s = (lane < cnt) ? g_ssrc[b + lane] : 0;
        #pragma unroll 4
        for (int j = 0; j < cnt; j++) {
            int sj = __shfl_sync(0xffffffffu, s, j);
            uint2 raw = *(const uint2*)(g_x16 + (size_t)sj * D + lane * 4);
            float2 f0 = __half22float2(*(__half2*)&raw.x);
            float2 f1 = __half22float2(*(__half2*)&raw.y);
            u64 p0, p1;
            asm("mov.b64 %0, {%1, %2};" : "=l"(p0) : "f"(f0.x), "f"(f0.y));
            asm("mov.b64 %0, {%1, %2};" : "=l"(p1) : "f"(f1.x), "f"(f1.y));
            asm("add.rn.f32x2 %0, %0, %1;" : "+l"(a01) : "l"(p0));
            asm("add.rn.f32x2 %0, %0, %1;" : "+l"(a23) : "l"(p1));
        }
    }
    float r0, r1, r2, r3;
    asm("mov.b64 {%0, %1}, %2;" : "=f"(r0), "=f"(r1) : "l"(a01));
    asm("mov.b64 {%0, %1}, %2;" : "=f"(r2), "=f"(r3) : "l"(a23));
    __half2 h0 = __floats2half2_rn(r0, r1);
    __half2 h1 = __floats2half2_rn(r2, r3);
    uint2 o;
    o.x = *(u32*)&h0; o.y = *(u32*)&h1;
    *(uint2*)(g_agg16 + (size_t)warp * D + lane * 4) = o;
}

// ---------------- K5: HMMA GEMM  h16 = [x16|agg16] @ B16 + br, + BN stats ----
// PDL: B tile and A stages 0-1 (the x16 half, incl. their MMAs) depend only on
// scan1's prologue (>=2 steps back) -> run BEFORE pdl_wait, overlapping k_agg.
// The wait sits right before the first agg16 cp.async (stage 2).
#define BS_ROWPAD 136               // halves per B row (128 + 8)
#define AS_ROWPAD 72                // halves per A row (64 + 8)
#define BS_BYTES  (256 * BS_ROWPAD * 2)          // 69632
#define AS_BYTES  (2 * 128 * AS_ROWPAD * 2)      // 36864
#define GEMM_SMEM (BS_BYTES + AS_BYTES)          // 106496

__device__ __forceinline__ void ldsm4(u32& r0, u32& r1, u32& r2, u32& r3, u32 a) {
    asm volatile("ldmatrix.sync.aligned.m8n8.x4.shared.b16 {%0,%1,%2,%3}, [%4];"
                 : "=r"(r0), "=r"(r1), "=r"(r2), "=r"(r3) : "r"(a));
}
__device__ __forceinline__ void ldsm4t(u32& r0, u32& r1, u32& r2, u32& r3, u32 a) {
    asm volatile("ldmatrix.sync.aligned.m8n8.x4.trans.shared.b16 {%0,%1,%2,%3}, [%4];"
                 : "=r"(r0), "=r"(r1), "=r"(r2), "=r"(r3) : "r"(a));
}
__device__ __forceinline__ void mma16816(float* c, u32 a0, u32 a1, u32 a2, u32 a3,
                                         u32 b0, u32 b1) {
    asm volatile("mma.sync.aligned.m16n8k16.row.col.f32.f16.f16.f32 "
                 "{%0,%1,%2,%3}, {%4,%5,%6,%7}, {%8,%9}, {%0,%1,%2,%3};"
                 : "+f"(c[0]), "+f"(c[1]), "+f"(c[2]), "+f"(c[3])
                 : "r"(a0), "r"(a1), "r"(a2), "r"(a3), "r"(b0), "r"(b1));
}
__device__ __forceinline__ void cpasync16(u32 saddr, const void* gptr, int zfill) {
    asm volatile("cp.async.cg.shared.global [%0], [%1], 16, %2;"
                 :: "r"(saddr), "l"(gptr), "r"(zfill));
}
__device__ __forceinline__ void cpasync_commit() {
    asm volatile("cp.async.commit_group;");
}
__device__ __forceinline__ void cpasync_wait0() {
    asm volatile("cp.async.wait_group 0;");
}

extern __shared__ char dynsm[];

__global__ __launch_bounds__(256, 2) void k_gemm() {
    __half* Bs = (__half*)dynsm;
    __half* As = (__half*)(dynsm + BS_BYTES);

    const int tid  = threadIdx.x;
    const int lane = tid & 31;
    const int wid  = tid >> 5;
    const int wm   = wid >> 1;      // 0..3
    const int wn   = wid & 1;       // 0..1
    const int m0   = blockIdx.x * 128;

    // ---- A stage copier: stage s covers k in [64s, 64s+64), cp.async 16B ----
    auto issueA = [&](int s, int buf) {
        const __half* src = (s < 2) ? g_x16 : g_agg16;
        int ko = (s < 2) ? s * 64 : (s - 2) * 64;
        #pragma unroll
        for (int j = 0; j < 4; j++) {
            int i = tid + j * 256;          // 1024 16B-chunks total
            int row = i >> 3, c = i & 7;
            int r = m0 + row;
            u32 saddr = (u32)__cvta_generic_to_shared(
                As + buf * 128 * AS_ROWPAD + row * AS_ROWPAD + c * 8);
            const void* g = src + (size_t)r * D + ko + c * 8;
            cpasync16(saddr, g, (r < N_NODES) ? 16 : 0);
        }
    };

    // ---- pre-wait prologue (x16/B16 from scan1's prologue, >=2 steps back) --
    issueA(0, 0);
    cpasync_commit();

    #pragma unroll
    for (int j = 0; j < 16; j++) {
        int i = tid + j * 256;              // 4096 float4 total
        int row = i >> 4, c = i & 15;
        float4 v = *(const float4*)(g_B16 + row * D + c * 8);
        *(float4*)(Bs + row * BS_ROWPAD + c * 8) = v;
    }

    cpasync_wait0();
    __syncthreads();

    // ---- per-lane ldmatrix addresses ----
    const int m_off = ((lane >> 3) & 1) * 8 + (lane & 7);
    const int k_off = (lane >> 4) * 8;
    const int kb_off = m_off;
    const int n_off = k_off;

    u32 a_base0 = (u32)__cvta_generic_to_shared(
        As + (wm * 32 + m_off) * AS_ROWPAD + k_off);
    u32 b_base = (u32)__cvta_generic_to_shared(
        Bs + kb_off * BS_ROWPAD + wn * 64 + n_off);

    float acc[2][8][4];
    #pragma unroll
    for (int mt = 0; mt < 2; mt++)
        #pragma unroll
        for (int nt = 0; nt < 8; nt++)
            #pragma unroll
            for (int q = 0; q < 4; q++) acc[mt][nt][q] = 0.f;

    #pragma unroll 1
    for (int s = 0; s < 4; s++) {
        const int buf = s & 1;
        if (s < 3) {                 // kick next-stage copy; overlaps with MMA
            if (s == 1) {            // stage 2 is the first agg16 read
                pdl_wait();          // k_agg must be complete
                pdl_launch_dependents();
            }
            issueA(s + 1, buf ^ 1);
            cpasync_commit();
        }
        const u32 a_stage = a_base0 + buf * (128 * AS_ROWPAD * 2);

        #pragma unroll
        for (int k16 = 0; k16 < 4; k16++) {
            u32 a[2][4];
            #pragma unroll
            for (int mt = 0; mt < 2; mt++)
                ldsm4(a[mt][0], a[mt][1], a[mt][2], a[mt][3],
                      a_stage + (mt * 16) * (AS_ROWPAD * 2) + k16 * 32);
            const u32 b_k = b_base + (s * 64 + k16 * 16) * (BS_ROWPAD * 2);
            #pragma unroll
            for (int np = 0; np < 4; np++) {
                u32 b0, b1, b2, b3;
                ldsm4t(b0, b1, b2, b3, b_k + np * 32);
                #pragma unroll
                for (int mt = 0; mt < 2; mt++) {
                    mma16816(acc[mt][np * 2],     a[mt][0], a[mt][1], a[mt][2], a[mt][3], b0, b1);
                    mma16816(acc[mt][np * 2 + 1], a[mt][0], a[mt][1], a[mt][2], a[mt][3], b2, b3);
                }
            }
        }
        if (s < 3) {
            cpasync_wait0();
            __syncthreads();
        }
    }

    // ---- epilogue: bias, store h16, BN partial stats (fp32, pre-rounding) ---
    const int qr = lane >> 2;     // 0..7
    const int qc = lane & 3;      // 0..3
    float s16[16], q16[16];
    #pragma unroll
    for (int t = 0; t < 16; t++) { s16[t] = 0.f; q16[t] = 0.f; }

    #pragma unroll
    for (int nt = 0; nt < 8; nt++) {
        const int col = wn * 64 + nt * 8 + qc * 2;
        const float2 br = *(const float2*)(g_br + col);
        #pragma unroll
        for (int mt = 0; mt < 2; mt++) {
            #pragma unroll
            for (int hh = 0; hh < 2; hh++) {   // c0c1 row, c2c3 row (+8)
                int r = m0 + wm * 32 + mt * 16 + qr + hh * 8;
                if (r >= N_NODES) continue;
                float v0 = acc[mt][nt][hh * 2]     + br.x;
                float v1 = acc[mt][nt][hh * 2 + 1] + br.y;
                *(__half2*)(g_h16 + (size_t)r * D + col) = __floats2half2_rn(v0, v1);
                s16[nt * 2]     += v0;  q16[nt * 2]     += v0 * v0;
                s16[nt * 2 + 1] += v1;  q16[nt * 2 + 1] += v1 * v1;
            }
        }
    }

    // ---- reduce stats: smem atomics then one global atomic per col ----
    __syncthreads();                 // all reads of As done; reuse as scratch
    float* sm_s = (float*)(dynsm + BS_BYTES);
    float* sm_q = sm_s + D;
    if (tid < D) { sm_s[tid] = 0.f; sm_q[tid] = 0.f; }
    __syncthreads();
    #pragma unroll
    for (int nt = 0; nt < 8; nt++) {
        int col = wn * 64 + nt * 8 + qc * 2;
        atomicAdd(&sm_s[col], s16[nt * 2]);
        atomicAdd(&sm_q[col], q16[nt * 2]);
        atomicAdd(&sm_s[col + 1], s16[nt * 2 + 1]);
        atomicAdd(&sm_q[col + 1], q16[nt * 2 + 1]);
    }
    __syncthreads();
    if (tid < D) {
        atomicAdd(&g_bnsum[tid], sm_s[tid]);
        atomicAdd(&g_bnsq[tid], sm_q[tid]);
    }
}

// ---------------- K6: BN finalize + pool (4-way row split) + classifier ------
// Also re-zeroes g_cnt for the next graph replay (g_cnt is dead by now).
__global__ __launch_bounds__(512) void k_final(
        const int* __restrict__ batch,
        const float* __restrict__ gamma, const float* __restrict__ beta,
        const float* __restrict__ Wc, const float* __restrict__ bc,
        float* __restrict__ out) {
    __shared__ float ps[D];
    __shared__ float smx[3][D];
    __shared__ float smn[3][D];
    const int g = blockIdx.x;
    const int tid = threadIdx.x;         // 0..511
    const int f = tid & 127;
    const int part = tid >> 7;           // 0..3

    // --- pre-wait prologue (independent of k_gemm's outputs) ---
    // zero degree counters for the next replay (512*512 threads cover 50000)
    int zid = g * 512 + tid;
    if (zid < N_NODES) g_cnt[zid] = 0;

    // binary search segment bounds over harness input (batch sorted)
    int lo = 0, hi = N_NODES;
    while (lo < hi) { int mid = (lo + hi) >> 1; if (batch[mid] < g) lo = mid + 1; else hi = mid; }
    int start = lo;
    hi = N_NODES;
    while (lo < hi) { int mid = (lo + hi) >> 1; if (batch[mid] < g + 1) lo = mid + 1; else hi = mid; }
    int end = lo;

    pdl_wait();                        // g_h16 / g_bnsum / g_bnsq must be final

    const float NEG_INF = __int_as_float(0xff800000);
    float mx = NEG_INF, mn = -NEG_INF;
    #pragma unroll 2
    for (int n = start + part; n < end; n += 4) {
        float v = __half2float(g_h16[(size_t)n * D + f]);
        mx = fmaxf(mx, v); mn = fminf(mn, v);
    }
    if (part) { smx[part - 1][f] = mx; smn[part - 1][f] = mn; }
    __syncthreads();

    if (part == 0) {
        #pragma unroll
        for (int p = 0; p < 3; p++) {
            mx = fmaxf(mx, smx[p][f]);
            mn = fminf(mn, smn[p][f]);
        }
        float mean = g_bnsum[f] * (1.f / N_NODES);
        float var  = g_bnsq[f] * (1.f / N_NODES) - mean * mean;
        float sc   = gamma[f] * rsqrtf(var + EPS);
        float sh   = beta[f] - mean * sc;
        float v;
        if (start == end) {
            v = 0.f;                       // empty segment: relu(-inf) = 0
        } else {
            float t = (sc >= 0.f) ? mx : mn;  // max-pool commutes with monotone affine
            v = fmaxf(fmaf(sc, t, sh), 0.f);
        }
        ps[f] = v;
    }
    __syncthreads();

    if (tid < 96) {
        float acc = bc[tid];
        const float4* w = (const float4*)(Wc + tid * D);
        const float4* p = (const float4*)ps;
        #pragma unroll
        for (int k = 0; k < D / 4; k++) {
            float4 wv = w[k], pv = p[k];
            acc += wv.x * pv.x + wv.y * pv.y + wv.z * pv.z + wv.w * pv.w;
        }
        out[g * 96 + tid] = acc;
    }
}

// ---------------- launch ------------------------------------------------------
extern "C" void kernel_launch(void* const* d_in, const int* in_sizes, int n_in,
                              void* d_out, int out_size) {
    const float* x     = (const float*)d_in[0];
    const int*   ei    = (const int*)d_in[1];   // [2, N_EDGES]: src then dst
    const int*   batch = (const int*)d_in[2];
    /* d_in[3] = i (unused, i=0 branch) */
    const float* Wrel  = (const float*)d_in[4];
    const float* brel  = (const float*)d_in[5];
    const float* Wroot = (const float*)d_in[6];
    const float* gamma = (const float*)d_in[7];
    const float* beta  = (const float*)d_in[8];
    const float* Wc    = (const float*)d_in[9];
    const float* bc    = (const float*)d_in[10];
    float* out = (float*)d_out;

    const int* src = ei;
    const int* dst = ei + N_EDGES;

    static int smem_set = 0;
    if (!smem_set) {
        cudaFuncSetAttribute(k_gemm, cudaFuncAttributeMaxDynamicSharedMemorySize,
                             GEMM_SMEM);
        smem_set = 1;
    }

    // PDL attribute: dependent launches may begin once the predecessor's CTAs
    // execute griddepcontrol.launch_dependents; device-side waits hold ordering.
    cudaLaunchAttribute pdl[1];
    pdl[0].id = cudaLaunchAttributeProgrammaticStreamSerialization;
    pdl[0].val.programmaticStreamSerializationAllowed = 1;

    // first kernel: plain launch (fully serialized vs previous replay's final,
    // which re-zeroes g_cnt)
    k_count<<<(N_EDGES + 255) / 256, 256>>>(dst);

    cudaLaunchConfig_t cfg = {};
    cfg.attrs = pdl;
    cfg.numAttrs = 1;

    cfg.gridDim = dim3(SCAN_GRID); cfg.blockDim = dim3(256); cfg.dynamicSmemBytes = 0;
    cudaLaunchKernelEx(&cfg, k_scan1, x, Wrel, brel, Wroot);

    cfg.gridDim = dim3((N_EDGES + 255) / 256); cfg.blockDim = dim3(256);
    cudaLaunchKernelEx(&cfg, k_scatter, src);

    cfg.gridDim = dim3((N_NODES * 32 + 255) / 256); cfg.blockDim = dim3(256);
    cudaLaunchKernelEx(&cfg, k_agg);

    cfg.gridDim = dim3((N_NODES + 127) / 128); cfg.blockDim = dim3(256);
    cfg.dynamicSmemBytes = GEMM_SMEM;
    cudaLaunchKernelEx(&cfg, k_gemm);

    cfg.gridDim = dim3(N_GRAPHS); cfg.blockDim = dim3(512); cfg.dynamicSmemBytes = 0;
    cudaLaunchKernelEx(&cfg, k_final, batch, gamma, beta, Wc, bc, out);
}

// round 17
// speedup vs baseline: 1.0053x; 1.0053x over previous
#include <cuda_runtime.h>
#include <cuda_fp16.h>
#include <cstdint>

#define N_NODES 50000
#define N_EDGES 800000
#define D 128
#define N_GRAPHS 512
#define N_CONVS 5
#define EPS 1e-5f

#define N_BLKS 196                  // ceil(50000/256)
#define OFF_SZ (N_BLKS * 256)       // 50176
#define SCAN_GRID 512               // 196 scan CTAs + 316 prologue-only CTAs

typedef unsigned long long u64;
typedef unsigned int u32;

// PDL: overlap dependent-kernel dispatch/prologue with predecessor execution.
// Contract: launch_dependents is executed AFTER this kernel's own pdl_wait
// (or at entry for the first kernel), so a successor's pre-wait code may only
// read data produced >= 2 dependency-steps back (transitively complete).
__device__ __forceinline__ void pdl_wait() {
    asm volatile("griddepcontrol.wait;" ::: "memory");
}
__device__ __forceinline__ void pdl_launch_dependents() {
    asm volatile("griddepcontrol.launch_dependents;" ::: "memory");
}

// ---------------- scratch (static device globals; no allocation) -------------
// NOTE: g_cnt is left zeroed at the END of each run (k_final), and g_ticket is
// reset by the last scan CTA of k_scan1, so every replay starts clean; device
// globals are zero-initialized at module load, so the first run is clean too.
__device__ int    g_cnt[N_NODES];
__device__ int    g_off[OFF_SZ];    // block-local exclusive offsets
__device__ int    g_bsum[N_BLKS];   // per-block sums
__device__ int    g_bpref[N_BLKS];  // exclusive prefix of block sums
__device__ int    g_ticket;         // last-CTA election for scan phase 2
__device__ int    g_slot[N_EDGES];  // packed (slot<<16) | dst
__device__ int    g_ssrc[N_EDGES];
__device__ __half g_x16[(size_t)N_NODES * D];
__device__ __half g_agg16[(size_t)N_NODES * D];
__device__ __half g_h16[(size_t)N_NODES * D];
__device__ __half g_B16[256 * D];   // folded weights, k-major: B[k][j], fp16
__device__ float  g_br[D];          // folded bias (fp32)
__device__ float  g_bnsum[D];
__device__ float  g_bnsq[D];

// ---------------- K1: degree count, 2 edges/thread (MLP=2 atomics) -----------
// Latency/atomic-bound; executes launch_dependents at ENTRY so k_scan1's CTAs
// launch as soon as slots free and their prologue co-runs with this tail.
__global__ void k_count(const int* __restrict__ dst) {
    pdl_launch_dependents();
    int i = (blockIdx.x * blockDim.x + threadIdx.x) * 2;
    if (i < N_EDGES) {                         // N_EDGES is even
        int2 d2 = *(const int2*)(dst + i);
        int s0 = atomicAdd(&g_cnt[d2.x], 1);   // two independent ATOMGs in flight
        int s1 = atomicAdd(&g_cnt[d2.y], 1);
        int2 pk;
        pk.x = (s0 << 16) | d2.x;              // d < 65536, slot << 65536
        pk.y = (s1 << 16) | d2.y;
        *(int2*)(g_slot + i) = pk;
    }
}

// ---------------- K2: [prologue: fold + x->fp16 + BN zero] + scan ------------
// All SCAN_GRID CTAs run the grid-stride prologue BEFORE pdl_wait (inputs are
// harness tensors only -> co-runs with k_count). Blocks >= N_BLKS then exit;
// blocks < N_BLKS wait for g_cnt and perform the hierarchical scan.
#define BFOLD     (256 * D)                      // 32768
#define X4_TOTAL  ((N_NODES * D) / 4)            // 1600000
#define PRO_TOTAL (BFOLD + D + 2 * D + X4_TOTAL)
__global__ void k_scan1(const float* __restrict__ x,
                        const float* __restrict__ Wrel,
                        const float* __restrict__ brel,
                        const float* __restrict__ Wroot) {
    __shared__ int wsum[8];
    const int t = threadIdx.x;
    const int lane = t & 31, w = t >> 5;

    // ---- pre-wait prologue (independent of k_count) ----
    for (int i = blockIdx.x * 256 + t; i < PRO_TOTAL; i += SCAN_GRID * 256) {
        if (i < BFOLD) {
            int k = i >> 7;          // 0..255 (A column)
            int j = i & 127;         // output feature
            float s = 0.f;
            if (k < D) {             // x half pairs with W_root
                #pragma unroll
                for (int c = 0; c < N_CONVS; c++) s += Wroot[c * D * D + j * D + k];
            } else {                 // agg half pairs with W_rel
                int kk = k - D;
                #pragma unroll
                for (int c = 0; c < N_CONVS; c++) s += Wrel[c * D * D + j * D + kk];
            }
            g_B16[i] = __float2half_rn(s);
        } else if (i < BFOLD + D) {
            int j = i - BFOLD;
            float s = 0.f;
            #pragma unroll
            for (int c = 0; c < N_CONVS; c++) s += brel[c * D + j];
            g_br[j] = s;
        } else if (i < BFOLD + 3 * D) {
            int j = i - (BFOLD + D);
            if (j < D) g_bnsum[j] = 0.f; else g_bnsq[j - D] = 0.f;
        } else {
            int e4 = i - (BFOLD + 3 * D);
            float4 v = ((const float4*)x)[e4];
            __half2* o = (__half2*)g_x16;
            o[e4 * 2]     = __floats2half2_rn(v.x, v.y);
            o[e4 * 2 + 1] = __floats2half2_rn(v.z, v.w);
        }
    }
    if (blockIdx.x >= N_BLKS) return;   // prologue-only CTAs

    pdl_wait();                        // g_cnt must be final
    pdl_launch_dependents();

    const int idx = blockIdx.x * 256 + t;
    int v = (idx < N_NODES) ? g_cnt[idx] : 0;
    int incl = v;
    #pragma unroll
    for (int d = 1; d < 32; d <<= 1) {
        int u = __shfl_up_sync(0xffffffffu, incl, d);
        if (lane >= d) incl += u;
    }
    if (lane == 31) wsum[w] = incl;
    __syncthreads();
    if (t < 8) {
        int x2 = wsum[t];
        int xi = x2;
        #pragma unroll
        for (int d = 1; d < 8; d <<= 1) {
            int u = __shfl_up_sync(0xffu, xi, d);
            if (t >= d) xi += u;
        }
        wsum[t] = xi;                  // inclusive warp-sum prefix
    }
    __syncthreads();
    int base = (w == 0) ? 0 : wsum[w - 1];
    g_off[idx] = base + incl - v;      // block-local exclusive
    if (t == 255) g_bsum[blockIdx.x] = wsum[7];

    // ---- phase 2: last scan CTA scans block sums ----
    __shared__ int is_last;
    __threadfence();                   // release g_bsum write
    if (t == 0) {
        int tk = atomicAdd(&g_ticket, 1);
        is_last = (tk == N_BLKS - 1);
    }
    __syncthreads();
    if (!is_last) return;
    __threadfence();                   // acquire all g_bsum writes

    int bv = (t < N_BLKS) ? g_bsum[t] : 0;
    int bincl = bv;
    #pragma unroll
    for (int d = 1; d < 32; d <<= 1) {
        int u = __shfl_up_sync(0xffffffffu, bincl, d);
        if (lane >= d) bincl += u;
    }
    __syncthreads();                   // wsum reuse safe
    if (lane == 31) wsum[w] = bincl;
    __syncthreads();
    if (t < 8) {
        int x2 = wsum[t];
        int xi = x2;
        #pragma unroll
        for (int d = 1; d < 8; d <<= 1) {
            int u = __shfl_up_sync(0xffu, xi, d);
            if (t >= d) xi += u;
        }
        wsum[t] = xi;
    }
    __syncthreads();
    int bbase = (w == 0) ? 0 : wsum[w - 1];
    if (t < N_BLKS) g_bpref[t] = bbase + bincl - bv;
    if (t == 0) g_ticket = 0;          // reset for next replay
}

// ---------------- K3: scatter edges into CSR (no atomics, packed slot) -------
__global__ void k_scatter(const int* __restrict__ src) {
    int i = blockIdx.x * blockDim.x + threadIdx.x;
    // pre-wait prologue: g_slot/src are k_count outputs (2 steps back)
    u32 pk = 0; int sv = 0;
    if (i < N_EDGES) { pk = (u32)g_slot[i]; sv = src[i]; }
    pdl_wait();                        // g_off/g_bpref (scan1) must be final
    pdl_launch_dependents();
    if (i < N_EDGES) {
        int d = pk & 0xFFFFu;
        int p = g_off[d] + g_bpref[d >> 8] + (int)(pk >> 16);
        g_ssrc[p] = sv;
    }
}

// ---------------- K4: aggregate (warp per node, packed f32x2, unroll 8) ------
// Latency-bound above its L2-traffic floor: double in-flight LDGs (unroll 8)
// and hoist the lane base address out of the loop.
__global__ void k_agg() {
    int warp = (blockIdx.x * blockDim.x + threadIdx.x) >> 5;
    int lane = threadIdx.x & 31;
    // pre-wait prologue: g_off/g_bpref are scan1 outputs (2 steps back)
    int e0 = 0, e1 = 0;
    if (warp < N_NODES) {
        e0 = g_off[warp] + g_bpref[warp >> 8];
        e1 = g_off[warp + 1] + g_bpref[(warp + 1) >> 8];
    }
    pdl_wait();                        // g_ssrc (scatter) must be final
    pdl_launch_dependents();
    if (warp >= N_NODES) return;

    const __half* xb = g_x16 + lane * 4;   // hoisted lane base
    u64 a01 = 0ull, a23 = 0ull;        // packed (f32,f32) accumulators
    for (int b = e0; b < e1; b += 32) {
        int cnt = min(32, e1 - b);
        int s = (lane < cnt) ? g_ssrc[b + lane] : 0;
        #pragma unroll 8
        for (int j = 0; j < cnt; j++) {
            int sj = __shfl_sync(0xffffffffu, s, j);
            uint2 raw = *(const uint2*)(xb + (size_t)sj * D);
            float2 f0 = __half22float2(*(__half2*)&raw.x);
            float2 f1 = __half22float2(*(__half2*)&raw.y);
            u64 p0, p1;
            asm("mov.b64 %0, {%1, %2};" : "=l"(p0) : "f"(f0.x), "f"(f0.y));
            asm("mov.b64 %0, {%1, %2};" : "=l"(p1) : "f"(f1.x), "f"(f1.y));
            asm("add.rn.f32x2 %0, %0, %1;" : "+l"(a01) : "l"(p0));
            asm("add.rn.f32x2 %0, %0, %1;" : "+l"(a23) : "l"(p1));
        }
    }
    float r0, r1, r2, r3;
    asm("mov.b64 {%0, %1}, %2;" : "=f"(r0), "=f"(r1) : "l"(a01));
    asm("mov.b64 {%0, %1}, %2;" : "=f"(r2), "=f"(r3) : "l"(a23));
    __half2 h0 = __floats2half2_rn(r0, r1);
    __half2 h1 = __floats2half2_rn(r2, r3);
    uint2 o;
    o.x = *(u32*)&h0; o.y = *(u32*)&h1;
    *(uint2*)(g_agg16 + (size_t)warp * D + lane * 4) = o;
}

// ---------------- K5: HMMA GEMM  h16 = [x16|agg16] @ B16 + br, + BN stats ----
// PDL: B tile and A stages 0-1 (the x16 half, incl. their MMAs) depend only on
// scan1's prologue (>=2 steps back) -> run BEFORE pdl_wait, overlapping k_agg.
// The wait sits right before the first agg16 cp.async (stage 2).
#define BS_ROWPAD 136               // halves per B row (128 + 8)
#define AS_ROWPAD 72                // halves per A row (64 + 8)
#define BS_BYTES  (256 * BS_ROWPAD * 2)          // 69632
#define AS_BYTES  (2 * 128 * AS_ROWPAD * 2)      // 36864
#define GEMM_SMEM (BS_BYTES + AS_BYTES)          // 106496

__device__ __forceinline__ void ldsm4(u32& r0, u32& r1, u32& r2, u32& r3, u32 a) {
    asm volatile("ldmatrix.sync.aligned.m8n8.x4.shared.b16 {%0,%1,%2,%3}, [%4];"
                 : "=r"(r0), "=r"(r1), "=r"(r2), "=r"(r3) : "r"(a));
}
__device__ __forceinline__ void ldsm4t(u32& r0, u32& r1, u32& r2, u32& r3, u32 a) {
    asm volatile("ldmatrix.sync.aligned.m8n8.x4.trans.shared.b16 {%0,%1,%2,%3}, [%4];"
                 : "=r"(r0), "=r"(r1), "=r"(r2), "=r"(r3) : "r"(a));
}
__device__ __forceinline__ void mma16816(float* c, u32 a0, u32 a1, u32 a2, u32 a3,
                                         u32 b0, u32 b1) {
    asm volatile("mma.sync.aligned.m16n8k16.row.col.f32.f16.f16.f32 "
                 "{%0,%1,%2,%3}, {%4,%5,%6,%7}, {%8,%9}, {%0,%1,%2,%3};"
                 : "+f"(c[0]), "+f"(c[1]), "+f"(c[2]), "+f"(c[3])
                 : "r"(a0), "r"(a1), "r"(a2), "r"(a3), "r"(b0), "r"(b1));
}
__device__ __forceinline__ void cpasync16(u32 saddr, const void* gptr, int zfill) {
    asm volatile("cp.async.cg.shared.global [%0], [%1], 16, %2;"
                 :: "r"(saddr), "l"(gptr), "r"(zfill));
}
__device__ __forceinline__ void cpasync_commit() {
    asm volatile("cp.async.commit_group;");
}
__device__ __forceinline__ void cpasync_wait0() {
    asm volatile("cp.async.wait_group 0;");
}

extern __shared__ char dynsm[];

__global__ __launch_bounds__(256, 2) void k_gemm() {
    __half* Bs = (__half*)dynsm;
    __half* As = (__half*)(dynsm + BS_BYTES);

    const int tid  = threadIdx.x;
    const int lane = tid & 31;
    const int wid  = tid >> 5;
    const int wm   = wid >> 1;      // 0..3
    const int wn   = wid & 1;       // 0..1
    const int m0   = blockIdx.x * 128;

    // ---- A stage copier: stage s covers k in [64s, 64s+64), cp.async 16B ----
    auto issueA = [&](int s, int buf) {
        const __half* src = (s < 2) ? g_x16 : g_agg16;
        int ko = (s < 2) ? s * 64 : (s - 2) * 64;
        #pragma unroll
        for (int j = 0; j < 4; j++) {
            int i = tid + j * 256;          // 1024 16B-chunks total
            int row = i >> 3, c = i & 7;
            int r = m0 + row;
            u32 saddr = (u32)__cvta_generic_to_shared(
                As + buf * 128 * AS_ROWPAD + row * AS_ROWPAD + c * 8);
            const void* g = src + (size_t)r * D + ko + c * 8;
            cpasync16(saddr, g, (r < N_NODES) ? 16 : 0);
        }
    };

    // ---- pre-wait prologue (x16/B16 from scan1's prologue, >=2 steps back) --
    issueA(0, 0);
    cpasync_commit();

    #pragma unroll
    for (int j = 0; j < 16; j++) {
        int i = tid + j * 256;              // 4096 float4 total
        int row = i >> 4, c = i & 15;
        float4 v = *(const float4*)(g_B16 + row * D + c * 8);
        *(float4*)(Bs + row * BS_ROWPAD + c * 8) = v;
    }

    cpasync_wait0();
    __syncthreads();

    // ---- per-lane ldmatrix addresses ----
    const int m_off = ((lane >> 3) & 1) * 8 + (lane & 7);
    const int k_off = (lane >> 4) * 8;
    const int kb_off = m_off;
    const int n_off = k_off;

    u32 a_base0 = (u32)__cvta_generic_to_shared(
        As + (wm * 32 + m_off) * AS_ROWPAD + k_off);
    u32 b_base = (u32)__cvta_generic_to_shared(
        Bs + kb_off * BS_ROWPAD + wn * 64 + n_off);

    float acc[2][8][4];
    #pragma unroll
    for (int mt = 0; mt < 2; mt++)
        #pragma unroll
        for (int nt = 0; nt < 8; nt++)
            #pragma unroll
            for (int q = 0; q < 4; q++) acc[mt][nt][q] = 0.f;

    #pragma unroll 1
    for (int s = 0; s < 4; s++) {
        const int buf = s & 1;
        if (s < 3) {                 // kick next-stage copy; overlaps with MMA
            if (s == 1) {            // stage 2 is the first agg16 read
                pdl_wait();          // k_agg must be complete
                pdl_launch_dependents();
            }
            issueA(s + 1, buf ^ 1);
            cpasync_commit();
        }
        const u32 a_stage = a_base0 + buf * (128 * AS_ROWPAD * 2);

        #pragma unroll
        for (int k16 = 0; k16 < 4; k16++) {
            u32 a[2][4];
            #pragma unroll
            for (int mt = 0; mt < 2; mt++)
                ldsm4(a[mt][0], a[mt][1], a[mt][2], a[mt][3],
                      a_stage + (mt * 16) * (AS_ROWPAD * 2) + k16 * 32);
            const u32 b_k = b_base + (s * 64 + k16 * 16) * (BS_ROWPAD * 2);
            #pragma unroll
            for (int np = 0; np < 4; np++) {
                u32 b0, b1, b2, b3;
                ldsm4t(b0, b1, b2, b3, b_k + np * 32);
                #pragma unroll
                for (int mt = 0; mt < 2; mt++) {
                    mma16816(acc[mt][np * 2],     a[mt][0], a[mt][1], a[mt][2], a[mt][3], b0, b1);
                    mma16816(acc[mt][np * 2 + 1], a[mt][0], a[mt][1], a[mt][2], a[mt][3], b2, b3);
                }
            }
        }
        if (s < 3) {
            cpasync_wait0();
            __syncthreads();
        }
    }

    // ---- epilogue: bias, store h16, BN partial stats (fp32, pre-rounding) ---
    const int qr = lane >> 2;     // 0..7
    const int qc = lane & 3;      // 0..3
    float s16[16], q16[16];
    #pragma unroll
    for (int t = 0; t < 16; t++) { s16[t] = 0.f; q16[t] = 0.f; }

    #pragma unroll
    for (int nt = 0; nt < 8; nt++) {
        const int col = wn * 64 + nt * 8 + qc * 2;
        const float2 br = *(const float2*)(g_br + col);
        #pragma unroll
        for (int mt = 0; mt < 2; mt++) {
            #pragma unroll
            for (int hh = 0; hh < 2; hh++) {   // c0c1 row, c2c3 row (+8)
                int r = m0 + wm * 32 + mt * 16 + qr + hh * 8;
                if (r >= N_NODES) continue;
                float v0 = acc[mt][nt][hh * 2]     + br.x;
                float v1 = acc[mt][nt][hh * 2 + 1] + br.y;
                *(__half2*)(g_h16 + (size_t)r * D + col) = __floats2half2_rn(v0, v1);
                s16[nt * 2]     += v0;  q16[nt * 2]     += v0 * v0;
                s16[nt * 2 + 1] += v1;  q16[nt * 2 + 1] += v1 * v1;
            }
        }
    }

    // ---- reduce stats: smem atomics then one global atomic per col ----
    __syncthreads();                 // all reads of As done; reuse as scratch
    float* sm_s = (float*)(dynsm + BS_BYTES);
    float* sm_q = sm_s + D;
    if (tid < D) { sm_s[tid] = 0.f; sm_q[tid] = 0.f; }
    __syncthreads();
    #pragma unroll
    for (int nt = 0; nt < 8; nt++) {
        int col = wn * 64 + nt * 8 + qc * 2;
        atomicAdd(&sm_s[col], s16[nt * 2]);
        atomicAdd(&sm_q[col], q16[nt * 2]);
        atomicAdd(&sm_s[col + 1], s16[nt * 2 + 1]);
        atomicAdd(&sm_q[col + 1], q16[nt * 2 + 1]);
    }
    __syncthreads();
    if (tid < D) {
        atomicAdd(&g_bnsum[tid], sm_s[tid]);
        atomicAdd(&g_bnsq[tid], sm_q[tid]);
    }
}

// ---------------- K6: BN finalize + pool (4-way row split) + classifier ------
// Also re-zeroes g_cnt for the next graph replay (g_cnt is dead by now).
__global__ __launch_bounds__(512) void k_final(
        const int* __restrict__ batch,
        const float* __restrict__ gamma, const float* __restrict__ beta,
        const float* __restrict__ Wc, const float* __restrict__ bc,
        float* __restrict__ out) {
    __shared__ float ps[D];
    __shared__ float smx[3][D];
    __shared__ float smn[3][D];
    const int g = blockIdx.x;
    const int tid = threadIdx.x;         // 0..511
    const int f = tid & 127;
    const int part = tid >> 7;           // 0..3

    // --- pre-wait prologue (independent of k_gemm's outputs) ---
    // zero degree counters for the next replay (512*512 threads cover 50000)
    int zid = g * 512 + tid;
    if (zid < N_NODES) g_cnt[zid] = 0;

    // binary search segment bounds over harness input (batch sorted)
    int lo = 0, hi = N_NODES;
    while (lo < hi) { int mid = (lo + hi) >> 1; if (batch[mid] < g) lo = mid + 1; else hi = mid; }
    int start = lo;
    hi = N_NODES;
    while (lo < hi) { int mid = (lo + hi) >> 1; if (batch[mid] < g + 1) lo = mid + 1; else hi = mid; }
    int end = lo;

    pdl_wait();                        // g_h16 / g_bnsum / g_bnsq must be final

    const float NEG_INF = __int_as_float(0xff800000);
    float mx = NEG_INF, mn = -NEG_INF;
    #pragma unroll 2
    for (int n = start + part; n < end; n += 4) {
        float v = __half2float(g_h16[(size_t)n * D + f]);
        mx = fmaxf(mx, v); mn = fminf(mn, v);
    }
    if (part) { smx[part - 1][f] = mx; smn[part - 1][f] = mn; }
    __syncthreads();

    if (part == 0) {
        #pragma unroll
        for (int p = 0; p < 3; p++) {
            mx = fmaxf(mx, smx[p][f]);
            mn = fminf(mn, smn[p][f]);
        }
        float mean = g_bnsum[f] * (1.f / N_NODES);
        float var  = g_bnsq[f] * (1.f / N_NODES) - mean * mean;
        float sc   = gamma[f] * rsqrtf(var + EPS);
        float sh   = beta[f] - mean * sc;
        float v;
        if (start == end) {
            v = 0.f;                       // empty segment: relu(-inf) = 0
        } else {
            float t = (sc >= 0.f) ? mx : mn;  // max-pool commutes with monotone affine
            v = fmaxf(fmaf(sc, t, sh), 0.f);
        }
        ps[f] = v;
    }
    __syncthreads();

    if (tid < 96) {
        float acc = bc[tid];
        const float4* w = (const float4*)(Wc + tid * D);
        const float4* p = (const float4*)ps;
        #pragma unroll
        for (int k = 0; k < D / 4; k++) {
            float4 wv = w[k], pv = p[k];
            acc += wv.x * pv.x + wv.y * pv.y + wv.z * pv.z + wv.w * pv.w;
        }
        out[g * 96 + tid] = acc;
    }
}

// ---------------- launch ------------------------------------------------------
extern "C" void kernel_launch(void* const* d_in, const int* in_sizes, int n_in,
                              void* d_out, int out_size) {
    const float* x     = (const float*)d_in[0];
    const int*   ei    = (const int*)d_in[1];   // [2, N_EDGES]: src then dst
    const int*   batch = (const int*)d_in[2];
    /* d_in[3] = i (unused, i=0 branch) */
    const float* Wrel  = (const float*)d_in[4];
    const float* brel  = (const float*)d_in[5];
    const float* Wroot = (const float*)d_in[6];
    const float* gamma = (const float*)d_in[7];
    const float* beta  = (const float*)d_in[8];
    const float* Wc    = (const float*)d_in[9];
    const float* bc    = (const float*)d_in[10];
    float* out = (float*)d_out;

    const int* src = ei;
    const int* dst = ei + N_EDGES;

    static int smem_set = 0;
    if (!smem_set) {
        cudaFuncSetAttribute(k_gemm, cudaFuncAttributeMaxDynamicSharedMemorySize,
                             GEMM_SMEM);
        smem_set = 1;
    }

    // PDL attribute: dependent launches may begin once the predecessor's CTAs
    // execute griddepcontrol.launch_dependents; device-side waits hold ordering.
    cudaLaunchAttribute pdl[1];
    pdl[0].id = cudaLaunchAttributeProgrammaticStreamSerialization;
    pdl[0].val.programmaticStreamSerializationAllowed = 1;

    // first kernel: plain launch (fully serialized vs previous replay's final,
    // which re-zeroes g_cnt)
    k_count<<<(N_EDGES / 2 + 255) / 256, 256>>>(dst);

    cudaLaunchConfig_t cfg = {};
    cfg.attrs = pdl;
    cfg.numAttrs = 1;

    cfg.gridDim = dim3(SCAN_GRID); cfg.blockDim = dim3(256); cfg.dynamicSmemBytes = 0;
    cudaLaunchKernelEx(&cfg, k_scan1, x, Wrel, brel, Wroot);

    cfg.gridDim = dim3((N_EDGES + 255) / 256); cfg.blockDim = dim3(256);
    cudaLaunchKernelEx(&cfg, k_scatter, src);

    cfg.gridDim = dim3((N_NODES * 32 + 255) / 256); cfg.blockDim = dim3(256);
    cudaLaunchKernelEx(&cfg, k_agg);

    cfg.gridDim = dim3((N_NODES + 127) / 128); cfg.blockDim = dim3(256);
    cfg.dynamicSmemBytes = GEMM_SMEM;
    cudaLaunchKernelEx(&cfg, k_gemm);

    cfg.gridDim = dim3(N_GRAPHS); cfg.blockDim = dim3(512); cfg.dynamicSmemBytes = 0;
    cudaLaunchKernelEx(&cfg, k_final, batch, gamma, beta, Wc, bc, out);
}